// round 5
// baseline (speedup 1.0000x reference)
#include <cuda_runtime.h>

typedef unsigned long long ull;

#define TW 128
#define TH 64
#define XW 132          // padded row stride in words (528B, 16B multiple)

__device__ __forceinline__ ull pk(float lo, float hi) {
    ull r;
    asm("mov.b64 %0, {%1,%2};" : "=l"(r) : "f"(lo), "f"(hi));
    return r;
}
__device__ __forceinline__ ull ffma2(ull a, ull b, ull c) {
    ull d;
    asm("fma.rn.f32x2 %0, %1, %2, %3;" : "=l"(d) : "l"(a), "l"(b), "l"(c));
    return d;
}
__device__ __forceinline__ ull fadd2(ull a, ull b) {
    ull d;
    asm("add.rn.f32x2 %0, %1, %2;" : "=l"(d) : "l"(a), "l"(b));
    return d;
}
// (a.hi, b.lo)
__device__ __forceinline__ ull cross(ull a, ull b) {
    ull r;
    asm("{\n\t"
        ".reg .b32 al, ah, bl, bh;\n\t"
        "mov.b64 {al, ah}, %1;\n\t"
        "mov.b64 {bl, bh}, %2;\n\t"
        "mov.b64 %0, {ah, bl};\n\t"
        "}" : "=l"(r) : "l"(a), "l"(b));
    return r;
}

// ---- tap macros: per (ci, phase) row, 3 kx taps feeding pairs A (pix0,1) and B (pix2,3)
#define _TAP3(CI, PH, T) \
    A0 = ffma2(wp[(T)],     Wa[CI][PH], A0); \
    B0 = ffma2(wp[(T)],     Wb[CI][PH], B0); \
    A1 = ffma2(wp[(T)+1], cross(Wa[CI][PH], Wb[CI][PH]), A1); \
    B1 = ffma2(wp[(T)+1], cross(Wb[CI][PH], Wc[CI][PH]), B1); \
    A0 = ffma2(wp[(T)+2], Wb[CI][PH], A0); \
    B0 = ffma2(wp[(T)+2], Wc[CI][PH], B0);

#define _TAPS(CI, PT, PM, PB) \
    _TAP3(CI, PT, (CI)*9 + 0) \
    _TAP3(CI, PM, (CI)*9 + 3) \
    _TAP3(CI, PB, (CI)*9 + 6)

#define ROWSTEP(R, PT, PM, PB) { \
    ull A0 = A0i, B0 = B0i, A1 = 0ULL, B1 = 0ULL; \
    if (row0 & ((R) == 0))  { A0 = fadd2(A0, addT_A); B0 = fadd2(B0, addT_B); } \
    if (row7 & ((R) == 63)) { A0 = fadd2(A0, addB_A); B0 = fadd2(B0, addB_B); } \
    _TAPS(0, PT, PM, PB) _TAPS(1, PT, PM, PB) _TAPS(2, PT, PM, PB) \
    ulonglong2 res; res.x = fadd2(A0, A1); res.y = fadd2(B0, B1); \
    *reinterpret_cast<ulonglong2*>(outbase + (size_t)(R) * 512) = res; }

#define REFILL(LI, PH) { \
    _Pragma("unroll") \
    for (int ci_ = 0; ci_ < 3; ci_++) { \
        const float* p_ = &xs[ci_][(LI) & 15][lw]; \
        ulonglong2 q_ = *reinterpret_cast<const ulonglong2*>(p_); \
        ull e_ = *reinterpret_cast<const ull*>(p_ + 4); \
        Wa[ci_][PH] = q_.x; Wb[ci_][PH] = q_.y; Wc[ci_][PH] = e_; } }

#define CHUNK6(R0) \
    ROWSTEP((R0)+0, 0,1,2)  REFILL((R0)+3, 0) \
    ROWSTEP((R0)+1, 1,2,0)  REFILL((R0)+4, 1) \
    ROWSTEP((R0)+2, 2,0,1)  REFILL((R0)+5, 2) \
    ROWSTEP((R0)+3, 0,1,2)  REFILL((R0)+6, 0) \
    ROWSTEP((R0)+4, 1,2,0)  REFILL((R0)+7, 1) \
    ROWSTEP((R0)+5, 2,0,1)  REFILL((R0)+8, 2)

// staged global->reg prefetch of NR input rows (3 ci, 130 cols each)
template<int NR>
__device__ __forceinline__ void ldg_rows(const float* __restrict__ x, int b,
                                         int hs, int w0, int tid, float* stg) {
    #pragma unroll
    for (int k = 0; k < (NR * 390 + 255) / 256; k++) {
        int i = tid + k * 256;
        float v = 0.f;
        if (i < NR * 390) {
            int ci = i / (NR * 130); int rem = i - ci * (NR * 130);
            int rr = rem / 130;      int col = rem - rr * 130;
            int gh = hs + rr, gw = w0 - 1 + col;
            if ((unsigned)gh < 512u && (unsigned)gw < 512u)
                v = x[((b * 3 + ci) * 512 + gh) * 512 + gw];
        }
        stg[k] = v;
    }
}
template<int NR>
__device__ __forceinline__ void sts_rows(float xs[3][16][XW], int h0, int hs,
                                         int tid, const float* stg) {
    #pragma unroll
    for (int k = 0; k < (NR * 390 + 255) / 256; k++) {
        int i = tid + k * 256;
        if (i < NR * 390) {
            int ci = i / (NR * 130); int rem = i - ci * (NR * 130);
            int rr = rem / 130;      int col = rem - rr * 130;
            int li = hs + rr - (h0 - 1);
            xs[ci][li & 15][col] = stg[k];
        }
    }
}

__global__ void __launch_bounds__(256, 1) conv_main(
    const float* __restrict__ x,   // [8,3,512,512]
    const float* __restrict__ ei,  // [8,192]
    const float* __restrict__ wm,  // [64,3,3,3]
    const float* __restrict__ bm,  // [64]
    const float* __restrict__ we,  // [64,3,3,3]
    const float* __restrict__ be,  // [64]
    float* __restrict__ out)       // [8,64,512,512]
{
    __shared__ __align__(16) float xs[3][16][XW];   // 16-slot rolling row buffer

    const int tid = threadIdx.x, lane = tid & 31, wid = tid >> 5;
    const int cx = blockIdx.x, ty = blockIdx.y;
    const int w0 = cx * TW, h0 = ty * TH;
    const int b = blockIdx.z >> 3, cg = blockIdx.z & 7;
    const int c = cg * 8 + wid;
    const int lw = lane * 4;

    // ---- channel weights -> registers as (w,w) pairs (once per CTA) ----
    ull wp[27];
    #pragma unroll
    for (int t = 0; t < 27; t++) {
        float w = __ldg(wm + c * 27 + t);
        wp[t] = pk(w, w);
    }

    // ---- extra-term scalars ----
    float S = 0, rT = 0, rB = 0, kL = 0, kR = 0;
    float tTL = 0, tTR = 0, tBL = 0, tBR = 0;
    #pragma unroll
    for (int e = 0; e < 3; e++) {
        float v = __ldg(ei + b * 192 + c * 3 + e);
        const float* wq = we + (c * 3 + e) * 9;
        #pragma unroll
        for (int ky = 0; ky < 3; ky++) {
            #pragma unroll
            for (int kx = 0; kx < 3; kx++) {
                float t = v * __ldg(wq + ky * 3 + kx);
                S += t;
                if (ky == 0) rT += t;
                if (ky == 2) rB += t;
                if (kx == 0) kL += t;
                if (kx == 2) kR += t;
                if (ky == 0 && kx == 0) tTL += t;
                if (ky == 0 && kx == 2) tTR += t;
                if (ky == 2 && kx == 0) tBL += t;
                if (ky == 2 && kx == 2) tBR += t;
            }
        }
    }
    const float basef = __ldg(bm + c) + __ldg(be + c) + S;
    const bool isL = (cx == 0) && (lane == 0);     // this thread owns global col 0 (pix A.lo)
    const bool isR = (cx == 3) && (lane == 31);    // owns global col 511 (pix B.hi)
    const ull A0i = pk(basef + (isL ? -kL : 0.f), basef);
    const ull B0i = pk(basef, basef + (isR ? -kR : 0.f));
    const ull addT_A = pk(-rT + (isL ? tTL : 0.f), -rT);
    const ull addT_B = pk(-rT, -rT + (isR ? tTR : 0.f));
    const ull addB_A = pk(-rB + (isL ? tBL : 0.f), -rB);
    const ull addB_B = pk(-rB, -rB + (isR ? tBR : 0.f));
    const bool row0 = (ty == 0), row7 = (ty == 7);

    // ---- prologue: stage 9 input rows h0-1 .. h0+7 into slots li 0..8 ----
    for (int i = tid; i < 3510; i += 256) {
        int ci = i / 1170; int rem = i - ci * 1170;
        int rr = rem / 130; int col = rem - rr * 130;
        int gh = h0 - 1 + rr, gw = w0 - 1 + col;
        float v = 0.f;
        if ((unsigned)gh < 512u && (unsigned)gw < 512u)
            v = x[((b * 3 + ci) * 512 + gh) * 512 + gw];
        xs[ci][rr][col] = v;
    }
    __syncthreads();

    // ---- init 3-row register window (li 0,1,2 -> phases 0,1,2) ----
    ull Wa[3][3], Wb[3][3], Wc[3][3];
    REFILL(0, 0) REFILL(1, 1) REFILL(2, 2)

    float* outbase = out + (((size_t)(b * 64 + c)) * 512 + h0) * 512 + w0 + lw;
    float stg[10];

    // ---- pipelined chunks: prefetch (regs) -> compute 6 rows -> STS -> barrier ----
    #pragma unroll 1
    for (int ch = 0; ch < 10; ch++) {
        const int hs = h0 + 6 * ch + 8;
        if (ch < 9) ldg_rows<6>(x, b, hs, w0, tid, stg);
        else        ldg_rows<3>(x, b, hs, w0, tid, stg);

        const int r0 = 6 * ch;
        CHUNK6(r0)

        if (ch < 9) sts_rows<6>(xs, h0, hs, tid, stg);
        else        sts_rows<3>(xs, h0, hs, tid, stg);
        __syncthreads();
    }

    // ---- tail rows 60..63 (window refills from li 63..65) ----
    ROWSTEP(60, 0,1,2)  REFILL(63, 0)
    ROWSTEP(61, 1,2,0)  REFILL(64, 1)
    ROWSTEP(62, 2,0,1)  REFILL(65, 2)
    ROWSTEP(63, 0,1,2)
}

extern "C" void kernel_launch(void* const* d_in, const int* in_sizes, int n_in,
                              void* d_out, int out_size)
{
    const float* x  = (const float*)d_in[0];
    const float* ei = (const float*)d_in[1];
    const float* wm = (const float*)d_in[2];
    const float* bm = (const float*)d_in[3];
    const float* we = (const float*)d_in[4];
    const float* be = (const float*)d_in[5];
    float* out = (float*)d_out;

    dim3 grid(4, 8, 64);   // colblocks x rowblocks x (batch*chgroup) = 2048 CTAs
    conv_main<<<grid, 256>>>(x, ei, wm, bm, we, be, out);
}

// round 6
// speedup vs baseline: 1.9255x; 1.9255x over previous
#include <cuda_runtime.h>

typedef unsigned long long ull;

#define HW 512
#define IMG (512 * 512)

// weight pairs, 64 ch x 9 rows x 4 slots (3 taps + pad), each slot (w,w) = 8B
// per row: exactly one 16B-aligned pair of LDC.128 (4 slots = 32B)
__constant__ ull c_wpair[64 * 36];
__device__ ull d_scratch[64 * 36];

__device__ __forceinline__ ull pk(float lo, float hi) {
    ull r;
    asm("mov.b64 %0, {%1,%2};" : "=l"(r) : "f"(lo), "f"(hi));
    return r;
}
__device__ __forceinline__ ull ffma2(ull a, ull b, ull c) {
    ull d;
    asm("fma.rn.f32x2 %0, %1, %2, %3;" : "=l"(d) : "l"(a), "l"(b), "l"(c));
    return d;
}
__device__ __forceinline__ ull fadd2(ull a, ull b) {
    ull d;
    asm("add.rn.f32x2 %0, %1, %2;" : "=l"(d) : "l"(a), "l"(b));
    return d;
}
// (a.hi, b.lo)
__device__ __forceinline__ ull cross(ull a, ull b) {
    ull r;
    asm("{\n\t"
        ".reg .b32 al, ah, bl, bh;\n\t"
        "mov.b64 {al, ah}, %1;\n\t"
        "mov.b64 {bl, bh}, %2;\n\t"
        "mov.b64 %0, {ah, bl};\n\t"
        "}" : "=l"(r) : "l"(a), "l"(b));
    return r;
}

__global__ void prep_weights(const float* __restrict__ wm) {
    int i = blockIdx.x * blockDim.x + threadIdx.x;   // over 64*36 slots
    if (i < 64 * 36) {
        int c = i / 36, s = i - c * 36, r = s >> 2, kx = s & 3;
        float v = (kx < 3) ? wm[c * 27 + r * 3 + kx] : 0.f;
        float* sf = (float*)d_scratch;
        sf[i * 2 + 0] = v;
        sf[i * 2 + 1] = v;
    }
}

// one tap-row: 3 taps x 4 accumulator pairs, weights from 2 LDC.128
#define TAPROW(R) { \
    ulonglong2 u0 = cw2[(R) * 2], u1 = cw2[(R) * 2 + 1]; \
    A  = ffma2(u0.x, W[R][0], A ); Bq = ffma2(u0.x, W[R][1], Bq); \
    Cq = ffma2(u0.x, W[R][2], Cq); D  = ffma2(u0.x, W[R][3], D ); \
    A  = ffma2(u0.y, W[R][5], A ); Bq = ffma2(u0.y, W[R][6], Bq); \
    Cq = ffma2(u0.y, W[R][7], Cq); D  = ffma2(u0.y, W[R][8], D ); \
    A  = ffma2(u1.x, W[R][1], A ); Bq = ffma2(u1.x, W[R][2], Bq); \
    Cq = ffma2(u1.x, W[R][3], Cq); D  = ffma2(u1.x, W[R][4], D ); }

#define CHLOOP(ROWADJ) \
    _Pragma("unroll 1") \
    for (int c = 0; c < 64; c++) { \
        const ulonglong2* cw2 = (const ulonglong2*)(c_wpair + c * 36); \
        ull bp = sBase[c]; \
        ull A = aptr[c], Bq = bp, Cq = bp, D = dptr[c]; \
        if (ROWADJ) { \
            float adj = rowc[c]; \
            float aL = adj + (isL ? cornL[c] : 0.f); \
            float aR = adj + (isR ? cornR[c] : 0.f); \
            ull adjp = pk(adj, adj); \
            A  = fadd2(A,  pk(aL, adj)); Bq = fadd2(Bq, adjp); \
            Cq = fadd2(Cq, adjp);        D  = fadd2(D,  pk(adj, aR)); \
        } \
        TAPROW(0) TAPROW(1) TAPROW(2) TAPROW(3) TAPROW(4) \
        TAPROW(5) TAPROW(6) TAPROW(7) TAPROW(8) \
        ulonglong2 r01; r01.x = A;  r01.y = Bq; \
        ulonglong2 r23; r23.x = Cq; r23.y = D; \
        float* op = outp + (size_t)c * IMG; \
        *reinterpret_cast<ulonglong2*>(op)     = r01; \
        *reinterpret_cast<ulonglong2*>(op + 4) = r23; \
    }

__global__ void __launch_bounds__(128, 2) conv_main(
    const float* __restrict__ x,   // [8,3,512,512]
    const float* __restrict__ ei,  // [8,192]
    const float* __restrict__ bm,  // [64]
    const float* __restrict__ we,  // [64,3,3,3]
    const float* __restrict__ be,  // [64]
    float* __restrict__ out)       // [8,64,512,512]
{
    __shared__ __align__(16) float xs[3][6][260];   // rows h0-1..h0+4, cols w0-1..w0+256
    __shared__ ull sBase[64], sBaseL[64], sBaseR[64];
    __shared__ float sCT[64], sCB[64], sTL[64], sTR[64], sBL[64], sBR[64];

    const int tid = threadIdx.x, lane = tid & 31, wid = tid >> 5;
    const int cx = blockIdx.x, ty = blockIdx.y, b = blockIdx.z;
    const int w0 = cx * 256, h0 = ty * 4;

    // ---- stage input patch (zero padded) ----
    for (int i = tid; i < 3 * 6 * 258; i += 128) {
        int ci = i / 1548;
        int rem = i - ci * 1548;
        int rr = rem / 258, j = rem - rr * 258;
        int gh = h0 - 1 + rr, gw = w0 - 1 + j;
        float v = 0.f;
        if ((unsigned)gh < 512u && (unsigned)gw < 512u)
            v = x[((b * 3 + ci) * HW + gh) * HW + gw];
        xs[ci][rr][j] = v;
    }

    // ---- per-channel extra-term scalars ----
    if (tid < 64) {
        int c = tid;
        float S = 0, rT = 0, rB = 0, kL = 0, kR = 0;
        float tTL = 0, tTR = 0, tBL = 0, tBR = 0;
        #pragma unroll
        for (int e = 0; e < 3; e++) {
            float v = __ldg(ei + b * 192 + c * 3 + e);
            const float* wq = we + (c * 3 + e) * 9;
            #pragma unroll
            for (int ky = 0; ky < 3; ky++) {
                #pragma unroll
                for (int kx = 0; kx < 3; kx++) {
                    float t = v * __ldg(wq + ky * 3 + kx);
                    S += t;
                    if (ky == 0) rT += t;
                    if (ky == 2) rB += t;
                    if (kx == 0) kL += t;
                    if (kx == 2) kR += t;
                    if (ky == 0 && kx == 0) tTL += t;
                    if (ky == 0 && kx == 2) tTR += t;
                    if (ky == 2 && kx == 0) tBL += t;
                    if (ky == 2 && kx == 2) tBR += t;
                }
            }
        }
        float base = __ldg(bm + c) + __ldg(be + c) + S;
        sBase[c]  = pk(base, base);
        sBaseL[c] = pk(base - kL, base);
        sBaseR[c] = pk(base, base - kR);
        sCT[c] = -rT; sCB[c] = -rB;
        sTL[c] = tTL; sTR[c] = tTR; sBL[c] = tBL; sBR[c] = tBR;
    }
    __syncthreads();

    // ---- build 9x9 register window: q0..q4 + crosses c01..c34 per (ci,dy) row ----
    ull W[9][9];
    #pragma unroll
    for (int ci = 0; ci < 3; ci++) {
        #pragma unroll
        for (int dy = 0; dy < 3; dy++) {
            const float* p = &xs[ci][wid + dy][lane * 8];
            ulonglong2 q01 = *reinterpret_cast<const ulonglong2*>(p);
            ulonglong2 q23 = *reinterpret_cast<const ulonglong2*>(p + 4);
            ull q4 = *reinterpret_cast<const ull*>(p + 8);
            int r = ci * 3 + dy;
            W[r][0] = q01.x; W[r][1] = q01.y; W[r][2] = q23.x;
            W[r][3] = q23.y; W[r][4] = q4;
            W[r][5] = cross(q01.x, q01.y);
            W[r][6] = cross(q01.y, q23.x);
            W[r][7] = cross(q23.x, q23.y);
            W[r][8] = cross(q23.y, q4);
        }
    }

    const int h = h0 + wid;
    const bool isL = (cx == 0) && (lane == 0);
    const bool isR = (cx == 1) && (lane == 31);
    const bool top = (h == 0), bot = (h == HW - 1);

    const ull* aptr = isL ? sBaseL : sBase;
    const ull* dptr = isR ? sBaseR : sBase;

    float* outp = out + (((size_t)b * 64) * HW + h) * HW + w0 + lane * 8;

    if (!(top | bot)) {
        const float* rowc = sCT;     // unused in this path
        const float* cornL = sTL;
        const float* cornR = sTR;
        (void)rowc; (void)cornL; (void)cornR;
        CHLOOP(false)
    } else {
        const float* rowc  = top ? sCT : sCB;
        const float* cornL = top ? sTL : sBL;
        const float* cornR = top ? sTR : sBR;
        CHLOOP(true)
    }
}

extern "C" void kernel_launch(void* const* d_in, const int* in_sizes, int n_in,
                              void* d_out, int out_size)
{
    const float* x  = (const float*)d_in[0];
    const float* ei = (const float*)d_in[1];
    const float* wm = (const float*)d_in[2];
    const float* bm = (const float*)d_in[3];
    const float* we = (const float*)d_in[4];
    const float* be = (const float*)d_in[5];
    float* out = (float*)d_out;

    prep_weights<<<(64 * 36 + 255) / 256, 256>>>(wm);

    void* scratch_ptr = nullptr;
    cudaGetSymbolAddress(&scratch_ptr, d_scratch);
    cudaMemcpyToSymbolAsync(c_wpair, scratch_ptr, sizeof(ull) * 64 * 36, 0,
                            cudaMemcpyDeviceToDevice, 0);

    dim3 grid(2, 128, 8);   // 2 col-blocks x 128 row-blocks x 8 batches = 2048 CTAs
    conv_main<<<grid, 128>>>(x, ei, bm, we, be, out);
}

// round 7
// speedup vs baseline: 2.1376x; 1.1102x over previous
#include <cuda_runtime.h>

typedef unsigned long long ull;

#define HW 512
#define IMG (512 * 512)

// weight pairs, 64 ch x 9 rows x 4 slots (w0,w1,w2,pad), each slot (w,w) = 8B
// per row: one 16B-aligned pair of LDC.128 (u0=(w0p,w1p), u1=(w2p,pad))
__constant__ ull c_wpair[64 * 36];
__device__ ull d_scratch[64 * 36];

__device__ __forceinline__ ull pk(float lo, float hi) {
    ull r;
    asm("mov.b64 %0, {%1,%2};" : "=l"(r) : "f"(lo), "f"(hi));
    return r;
}
__device__ __forceinline__ ull ffma2(ull a, ull b, ull c) {
    ull d;
    asm("fma.rn.f32x2 %0, %1, %2, %3;" : "=l"(d) : "l"(a), "l"(b), "l"(c));
    return d;
}
__device__ __forceinline__ ull fadd2(ull a, ull b) {
    ull d;
    asm("add.rn.f32x2 %0, %1, %2;" : "=l"(d) : "l"(a), "l"(b));
    return d;
}
// (a.hi, b.lo)
__device__ __forceinline__ ull cross(ull a, ull b) {
    ull r;
    asm("{\n\t"
        ".reg .b32 al, ah, bl, bh;\n\t"
        "mov.b64 {al, ah}, %1;\n\t"
        "mov.b64 {bl, bh}, %2;\n\t"
        "mov.b64 %0, {ah, bl};\n\t"
        "}" : "=l"(r) : "l"(a), "l"(b));
    return r;
}

__global__ void prep_weights(const float* __restrict__ wm) {
    int i = blockIdx.x * blockDim.x + threadIdx.x;   // over 64*36 slots
    if (i < 64 * 36) {
        int c = i / 36, s = i - c * 36, r = s >> 2, kx = s & 3;
        float v = (kx < 3) ? wm[c * 27 + r * 3 + kx] : 0.f;
        float* sf = (float*)d_scratch;
        sf[i * 2 + 0] = v;
        sf[i * 2 + 1] = v;
    }
}

// one tap-row, aligned pairs only: F_j += w0*q_j + w2*q_{j+1};  E_j += w1*q_j
#define TAPROW(R) { \
    ulonglong2 u0 = cw2[(R) * 2], u1 = cw2[(R) * 2 + 1]; \
    F0 = ffma2(u0.x, W[R][0], F0); F1 = ffma2(u0.x, W[R][1], F1); \
    F2 = ffma2(u0.x, W[R][2], F2); F3 = ffma2(u0.x, W[R][3], F3); \
    E0 = ffma2(u0.y, W[R][0], E0); E1 = ffma2(u0.y, W[R][1], E1); \
    E2 = ffma2(u0.y, W[R][2], E2); E3 = ffma2(u0.y, W[R][3], E3); \
    E4 = ffma2(u0.y, W[R][4], E4); \
    F0 = ffma2(u1.x, W[R][1], F0); F1 = ffma2(u1.x, W[R][2], F1); \
    F2 = ffma2(u1.x, W[R][3], F2); F3 = ffma2(u1.x, W[R][4], F3); }

#define CHLOOP(ROWADJ) \
    _Pragma("unroll 1") \
    for (int c = 0; c < 64; c++) { \
        const ulonglong2* cw2 = (const ulonglong2*)(c_wpair + c * 36); \
        ull bp = sBase[c]; \
        ull F0 = aptr[c], F1 = bp, F2 = bp, F3 = dptr[c]; \
        ull E0 = 0ULL, E1 = 0ULL, E2 = 0ULL, E3 = 0ULL, E4 = 0ULL; \
        if (ROWADJ) { \
            float adj = rowc[c]; \
            float aL = adj + (isL ? cornL[c] : 0.f); \
            float aR = adj + (isR ? cornR[c] : 0.f); \
            ull adjp = pk(adj, adj); \
            F0 = fadd2(F0, pk(aL, adj)); F1 = fadd2(F1, adjp); \
            F2 = fadd2(F2, adjp);        F3 = fadd2(F3, pk(adj, aR)); \
        } \
        TAPROW(0) TAPROW(1) TAPROW(2) TAPROW(3) TAPROW(4) \
        TAPROW(5) TAPROW(6) TAPROW(7) TAPROW(8) \
        ulonglong2 r01, r23; \
        r01.x = fadd2(F0, cross(E0, E1)); \
        r01.y = fadd2(F1, cross(E1, E2)); \
        r23.x = fadd2(F2, cross(E2, E3)); \
        r23.y = fadd2(F3, cross(E3, E4)); \
        float* op = outp + (size_t)c * IMG; \
        *reinterpret_cast<ulonglong2*>(op)     = r01; \
        *reinterpret_cast<ulonglong2*>(op + 4) = r23; \
    }

__global__ void __launch_bounds__(128, 3) conv_main(
    const float* __restrict__ x,   // [8,3,512,512]
    const float* __restrict__ ei,  // [8,192]
    const float* __restrict__ bm,  // [64]
    const float* __restrict__ we,  // [64,3,3,3]
    const float* __restrict__ be,  // [64]
    float* __restrict__ out)       // [8,64,512,512]
{
    __shared__ __align__(16) float xs[3][6][260];   // rows h0-1..h0+4, cols w0-1..w0+256
    __shared__ ull sBase[64], sBaseL[64], sBaseR[64];
    __shared__ float sCT[64], sCB[64], sTL[64], sTR[64], sBL[64], sBR[64];

    const int tid = threadIdx.x, lane = tid & 31, wid = tid >> 5;
    const int cx = blockIdx.x, ty = blockIdx.y, b = blockIdx.z;
    const int w0 = cx * 256, h0 = ty * 4;

    // ---- stage input patch (zero padded) ----
    for (int i = tid; i < 3 * 6 * 258; i += 128) {
        int ci = i / 1548;
        int rem = i - ci * 1548;
        int rr = rem / 258, j = rem - rr * 258;
        int gh = h0 - 1 + rr, gw = w0 - 1 + j;
        float v = 0.f;
        if ((unsigned)gh < 512u && (unsigned)gw < 512u)
            v = x[((b * 3 + ci) * HW + gh) * HW + gw];
        xs[ci][rr][j] = v;
    }

    // ---- per-channel extra-term scalars ----
    if (tid < 64) {
        int c = tid;
        float S = 0, rT = 0, rB = 0, kL = 0, kR = 0;
        float tTL = 0, tTR = 0, tBL = 0, tBR = 0;
        #pragma unroll
        for (int e = 0; e < 3; e++) {
            float v = __ldg(ei + b * 192 + c * 3 + e);
            const float* wq = we + (c * 3 + e) * 9;
            #pragma unroll
            for (int ky = 0; ky < 3; ky++) {
                #pragma unroll
                for (int kx = 0; kx < 3; kx++) {
                    float t = v * __ldg(wq + ky * 3 + kx);
                    S += t;
                    if (ky == 0) rT += t;
                    if (ky == 2) rB += t;
                    if (kx == 0) kL += t;
                    if (kx == 2) kR += t;
                    if (ky == 0 && kx == 0) tTL += t;
                    if (ky == 0 && kx == 2) tTR += t;
                    if (ky == 2 && kx == 0) tBL += t;
                    if (ky == 2 && kx == 2) tBR += t;
                }
            }
        }
        float base = __ldg(bm + c) + __ldg(be + c) + S;
        sBase[c]  = pk(base, base);
        sBaseL[c] = pk(base - kL, base);
        sBaseR[c] = pk(base, base - kR);
        sCT[c] = -rT; sCB[c] = -rB;
        sTL[c] = tTL; sTR[c] = tTR; sBL[c] = tBL; sBR[c] = tBR;
    }
    __syncthreads();

    // ---- build 9x5 register window of aligned pairs q0..q4 per (ci,dy) row ----
    ull W[9][5];
    #pragma unroll
    for (int ci = 0; ci < 3; ci++) {
        #pragma unroll
        for (int dy = 0; dy < 3; dy++) {
            const float* p = &xs[ci][wid + dy][lane * 8];
            ulonglong2 q01 = *reinterpret_cast<const ulonglong2*>(p);
            ulonglong2 q23 = *reinterpret_cast<const ulonglong2*>(p + 4);
            ull q4 = *reinterpret_cast<const ull*>(p + 8);
            int r = ci * 3 + dy;
            W[r][0] = q01.x; W[r][1] = q01.y; W[r][2] = q23.x;
            W[r][3] = q23.y; W[r][4] = q4;
        }
    }

    const int h = h0 + wid;
    const bool isL = (cx == 0) && (lane == 0);
    const bool isR = (cx == 1) && (lane == 31);
    const bool top = (h == 0), bot = (h == HW - 1);

    const ull* aptr = isL ? sBaseL : sBase;
    const ull* dptr = isR ? sBaseR : sBase;

    float* outp = out + (((size_t)b * 64) * HW + h) * HW + w0 + lane * 8;

    if (!(top | bot)) {
        const float* rowc = sCT;
        const float* cornL = sTL;
        const float* cornR = sTR;
        (void)rowc; (void)cornL; (void)cornR;
        CHLOOP(false)
    } else {
        const float* rowc  = top ? sCT : sCB;
        const float* cornL = top ? sTL : sBL;
        const float* cornR = top ? sTR : sBR;
        CHLOOP(true)
    }
}

extern "C" void kernel_launch(void* const* d_in, const int* in_sizes, int n_in,
                              void* d_out, int out_size)
{
    const float* x  = (const float*)d_in[0];
    const float* ei = (const float*)d_in[1];
    const float* wm = (const float*)d_in[2];
    const float* bm = (const float*)d_in[3];
    const float* we = (const float*)d_in[4];
    const float* be = (const float*)d_in[5];
    float* out = (float*)d_out;

    prep_weights<<<(64 * 36 + 255) / 256, 256>>>(wm);

    void* scratch_ptr = nullptr;
    cudaGetSymbolAddress(&scratch_ptr, d_scratch);
    cudaMemcpyToSymbolAsync(c_wpair, scratch_ptr, sizeof(ull) * 64 * 36, 0,
                            cudaMemcpyDeviceToDevice, 0);

    dim3 grid(2, 128, 8);   // 2 col-blocks x 128 row-blocks x 8 batches = 2048 CTAs
    conv_main<<<grid, 128>>>(x, ei, bm, we, be, out);
}

// round 8
// speedup vs baseline: 2.2144x; 1.0359x over previous
#include <cuda_runtime.h>

typedef unsigned long long ull;

#define HW 512
#define IMG (512 * 512)

// weight layout per channel: 28 ull slots (224B, 16B-aligned)
//  slots 0..17 : 9 rows x (w0pair, w2pair)  -> 9 LDC.128, both halves useful
//  slots 18..26: w1pair rows 0..8           -> 5 LDC.128 (last half = pad)
//  slot  27    : pad
__constant__ ull c_wpair[64 * 28];
__device__ ull d_scratch[64 * 28];

__device__ __forceinline__ ull pk(float lo, float hi) {
    ull r;
    asm("mov.b64 %0, {%1,%2};" : "=l"(r) : "f"(lo), "f"(hi));
    return r;
}
__device__ __forceinline__ ull ffma2(ull a, ull b, ull c) {
    ull d;
    asm("fma.rn.f32x2 %0, %1, %2, %3;" : "=l"(d) : "l"(a), "l"(b), "l"(c));
    return d;
}
__device__ __forceinline__ ull fadd2(ull a, ull b) {
    ull d;
    asm("add.rn.f32x2 %0, %1, %2;" : "=l"(d) : "l"(a), "l"(b));
    return d;
}
// (a.hi, b.lo)
__device__ __forceinline__ ull cross(ull a, ull b) {
    ull r;
    asm("{\n\t"
        ".reg .b32 al, ah, bl, bh;\n\t"
        "mov.b64 {al, ah}, %1;\n\t"
        "mov.b64 {bl, bh}, %2;\n\t"
        "mov.b64 %0, {ah, bl};\n\t"
        "}" : "=l"(r) : "l"(a), "l"(b));
    return r;
}

__global__ void prep_weights(const float* __restrict__ wm) {
    int i = blockIdx.x * blockDim.x + threadIdx.x;   // over 64*28 slots
    if (i < 64 * 28) {
        int c = i / 28, s = i - c * 28;
        float v = 0.f;
        if (s < 18) {
            int r = s >> 1, which = s & 1;           // 0 -> w0, 1 -> w2
            v = wm[c * 27 + r * 3 + (which ? 2 : 0)];
        } else if (s < 27) {
            int r = s - 18;
            v = wm[c * 27 + r * 3 + 1];              // w1
        }
        float* sf = (float*)d_scratch;
        sf[i * 2 + 0] = v;
        sf[i * 2 + 1] = v;
    }
}

// F-taps for one row: one LDC.128 gives (w0pair, w2pair)
#define TAPF(R) { \
    ulonglong2 u = cwF[R]; \
    F0 = ffma2(u.x, W[R][0], F0); F1 = ffma2(u.x, W[R][1], F1); \
    F2 = ffma2(u.x, W[R][2], F2); F3 = ffma2(u.x, W[R][3], F3); \
    F0 = ffma2(u.y, W[R][1], F0); F1 = ffma2(u.y, W[R][2], F1); \
    F2 = ffma2(u.y, W[R][3], F2); F3 = ffma2(u.y, W[R][4], F3); }

// E-taps for one row with given w1 pair
#define TAPE(R, WP) { \
    E0 = ffma2(WP, W[R][0], E0); E1 = ffma2(WP, W[R][1], E1); \
    E2 = ffma2(WP, W[R][2], E2); E3 = ffma2(WP, W[R][3], E3); \
    E4 = ffma2(WP, W[R][4], E4); }

#define CHLOOP(ROWADJ) \
    _Pragma("unroll 1") \
    for (int c = 0; c < 64; c++) { \
        const ulonglong2* cwF = (const ulonglong2*)(c_wpair + c * 28); \
        const ulonglong2* cwE = (const ulonglong2*)(c_wpair + c * 28 + 18); \
        ull bp = sBase[c]; \
        ull F0 = aptr[c], F1 = bp, F2 = bp, F3 = dptr[c]; \
        ull E0 = 0ULL, E1 = 0ULL, E2 = 0ULL, E3 = 0ULL, E4 = 0ULL; \
        if (ROWADJ) { \
            float adj = rowc[c]; \
            float aL = adj + (isL ? cornL[c] : 0.f); \
            float aR = adj + (isR ? cornR[c] : 0.f); \
            ull adjp = pk(adj, adj); \
            F0 = fadd2(F0, pk(aL, adj)); F1 = fadd2(F1, adjp); \
            F2 = fadd2(F2, adjp);        F3 = fadd2(F3, pk(adj, aR)); \
        } \
        TAPF(0) TAPF(1) TAPF(2) TAPF(3) TAPF(4) \
        TAPF(5) TAPF(6) TAPF(7) TAPF(8) \
        { ulonglong2 v = cwE[0]; TAPE(0, v.x) TAPE(1, v.y) } \
        { ulonglong2 v = cwE[1]; TAPE(2, v.x) TAPE(3, v.y) } \
        { ulonglong2 v = cwE[2]; TAPE(4, v.x) TAPE(5, v.y) } \
        { ulonglong2 v = cwE[3]; TAPE(6, v.x) TAPE(7, v.y) } \
        { ulonglong2 v = cwE[4]; TAPE(8, v.x) } \
        ulonglong2 r01, r23; \
        r01.x = fadd2(F0, cross(E0, E1)); \
        r01.y = fadd2(F1, cross(E1, E2)); \
        r23.x = fadd2(F2, cross(E2, E3)); \
        r23.y = fadd2(F3, cross(E3, E4)); \
        float* op = outp + (size_t)c * IMG; \
        *reinterpret_cast<ulonglong2*>(op)     = r01; \
        *reinterpret_cast<ulonglong2*>(op + 4) = r23; \
    }

__global__ void __launch_bounds__(128, 4) conv_main(
    const float* __restrict__ x,   // [8,3,512,512]
    const float* __restrict__ ei,  // [8,192]
    const float* __restrict__ bm,  // [64]
    const float* __restrict__ we,  // [64,3,3,3]
    const float* __restrict__ be,  // [64]
    float* __restrict__ out)       // [8,64,512,512]
{
    __shared__ __align__(16) float xs[3][6][260];   // rows h0-1..h0+4, cols w0-1..w0+256
    __shared__ ull sBase[64], sBaseL[64], sBaseR[64];
    __shared__ float sCT[64], sCB[64], sTL[64], sTR[64], sBL[64], sBR[64];

    const int tid = threadIdx.x, lane = tid & 31, wid = tid >> 5;
    const int cx = blockIdx.x, ty = blockIdx.y, b = blockIdx.z;
    const int w0 = cx * 256, h0 = ty * 4;

    // ---- stage input patch (zero padded) ----
    for (int i = tid; i < 3 * 6 * 258; i += 128) {
        int ci = i / 1548;
        int rem = i - ci * 1548;
        int rr = rem / 258, j = rem - rr * 258;
        int gh = h0 - 1 + rr, gw = w0 - 1 + j;
        float v = 0.f;
        if ((unsigned)gh < 512u && (unsigned)gw < 512u)
            v = x[((b * 3 + ci) * HW + gh) * HW + gw];
        xs[ci][rr][j] = v;
    }

    // ---- per-channel extra-term scalars ----
    if (tid < 64) {
        int c = tid;
        float S = 0, rT = 0, rB = 0, kL = 0, kR = 0;
        float tTL = 0, tTR = 0, tBL = 0, tBR = 0;
        #pragma unroll
        for (int e = 0; e < 3; e++) {
            float v = __ldg(ei + b * 192 + c * 3 + e);
            const float* wq = we + (c * 3 + e) * 9;
            #pragma unroll
            for (int ky = 0; ky < 3; ky++) {
                #pragma unroll
                for (int kx = 0; kx < 3; kx++) {
                    float t = v * __ldg(wq + ky * 3 + kx);
                    S += t;
                    if (ky == 0) rT += t;
                    if (ky == 2) rB += t;
                    if (kx == 0) kL += t;
                    if (kx == 2) kR += t;
                    if (ky == 0 && kx == 0) tTL += t;
                    if (ky == 0 && kx == 2) tTR += t;
                    if (ky == 2 && kx == 0) tBL += t;
                    if (ky == 2 && kx == 2) tBR += t;
                }
            }
        }
        float base = __ldg(bm + c) + __ldg(be + c) + S;
        sBase[c]  = pk(base, base);
        sBaseL[c] = pk(base - kL, base);
        sBaseR[c] = pk(base, base - kR);
        sCT[c] = -rT; sCB[c] = -rB;
        sTL[c] = tTL; sTR[c] = tTR; sBL[c] = tBL; sBR[c] = tBR;
    }
    __syncthreads();

    // ---- build 9x5 register window of aligned pairs q0..q4 per (ci,dy) row ----
    ull W[9][5];
    #pragma unroll
    for (int ci = 0; ci < 3; ci++) {
        #pragma unroll
        for (int dy = 0; dy < 3; dy++) {
            const float* p = &xs[ci][wid + dy][lane * 8];
            ulonglong2 q01 = *reinterpret_cast<const ulonglong2*>(p);
            ulonglong2 q23 = *reinterpret_cast<const ulonglong2*>(p + 4);
            ull q4 = *reinterpret_cast<const ull*>(p + 8);
            int r = ci * 3 + dy;
            W[r][0] = q01.x; W[r][1] = q01.y; W[r][2] = q23.x;
            W[r][3] = q23.y; W[r][4] = q4;
        }
    }

    const int h = h0 + wid;
    const bool isL = (cx == 0) && (lane == 0);
    const bool isR = (cx == 1) && (lane == 31);
    const bool top = (h == 0), bot = (h == HW - 1);

    const ull* aptr = isL ? sBaseL : sBase;
    const ull* dptr = isR ? sBaseR : sBase;

    float* outp = out + (((size_t)b * 64) * HW + h) * HW + w0 + lane * 8;

    if (!(top | bot)) {
        const float* rowc = sCT;
        const float* cornL = sTL;
        const float* cornR = sTR;
        (void)rowc; (void)cornL; (void)cornR;
        CHLOOP(false)
    } else {
        const float* rowc  = top ? sCT : sCB;
        const float* cornL = top ? sTL : sBL;
        const float* cornR = top ? sTR : sBR;
        CHLOOP(true)
    }
}

extern "C" void kernel_launch(void* const* d_in, const int* in_sizes, int n_in,
                              void* d_out, int out_size)
{
    const float* x  = (const float*)d_in[0];
    const float* ei = (const float*)d_in[1];
    const float* wm = (const float*)d_in[2];
    const float* bm = (const float*)d_in[3];
    const float* we = (const float*)d_in[4];
    const float* be = (const float*)d_in[5];
    float* out = (float*)d_out;

    prep_weights<<<(64 * 28 + 255) / 256, 256>>>(wm);

    void* scratch_ptr = nullptr;
    cudaGetSymbolAddress(&scratch_ptr, d_scratch);
    cudaMemcpyToSymbolAsync(c_wpair, scratch_ptr, sizeof(ull) * 64 * 28, 0,
                            cudaMemcpyDeviceToDevice, 0);

    dim3 grid(2, 128, 8);   // 2 col-blocks x 128 row-blocks x 8 batches = 2048 CTAs
    conv_main<<<grid, 128>>>(x, ei, bm, we, be, out);
}